// round 1
// baseline (speedup 1.0000x reference)
#include <cuda_runtime.h>
#include <cstdint>
#include <cstdio>

#define LN_EPS 1e-6f

// ============================================================
// LayerNorm: one row (H=1024) per block of 256 threads, float4
// ============================================================
__global__ void ln_kernel(const float* __restrict__ x,
                          const float* __restrict__ scale,
                          const float* __restrict__ bias,
                          float* __restrict__ ln_out, int H) {
    int row = blockIdx.x;
    const float4* xr = reinterpret_cast<const float4*>(x + (size_t)row * H);
    float4 v = xr[threadIdx.x];

    float s  = v.x + v.y + v.z + v.w;
    float sq = v.x * v.x + v.y * v.y + v.z * v.z + v.w * v.w;
    #pragma unroll
    for (int o = 16; o > 0; o >>= 1) {
        s  += __shfl_xor_sync(0xffffffffu, s,  o);
        sq += __shfl_xor_sync(0xffffffffu, sq, o);
    }
    __shared__ float ssum[8], ssq[8];
    int wid = threadIdx.x >> 5, lid = threadIdx.x & 31;
    if (lid == 0) { ssum[wid] = s; ssq[wid] = sq; }
    __syncthreads();
    s = 0.f; sq = 0.f;
    #pragma unroll
    for (int i = 0; i < 8; i++) { s += ssum[i]; sq += ssq[i]; }

    float invH = 1.0f / (float)H;
    float mu   = s * invH;
    float var  = sq * invH - mu * mu;
    float rstd = rsqrtf(var + LN_EPS);

    float4 sc = reinterpret_cast<const float4*>(scale)[threadIdx.x];
    float4 bi = reinterpret_cast<const float4*>(bias)[threadIdx.x];
    float4 o;
    o.x = (v.x - mu) * rstd * sc.x + bi.x;
    o.y = (v.y - mu) * rstd * sc.y + bi.y;
    o.z = (v.z - mu) * rstd * sc.z + bi.z;
    o.w = (v.w - mu) * rstd * sc.w + bi.w;
    reinterpret_cast<float4*>(ln_out + (size_t)row * H)[threadIdx.x] = o;
}

// ============================================================
// TF32 GEMM: C[M,N] = A[M,K] * B[K,N], all row-major fp32.
// BM=128 BN=128 BK=32, 256 threads (8 warps: 4 m-rows x 2 n-cols),
// warp tile 32x64, mma.sync.m16n8k8 tf32 (cvt.rna rounding),
// cp.async double-buffered shared memory.
// ============================================================
#define BM 128
#define BN 128
#define BK 32
#define AS_STRIDE 36   // BK + 4 : 4*gid + tig bijective mod 32 -> conflict-free A frags
#define BS_STRIDE 136  // BN + 8 : 8*tig + gid bijective mod 32 -> conflict-free B frags
#define AS_SIZE (BM * AS_STRIDE)   // 4608 floats
#define BS_SIZE (BK * BS_STRIDE)   // 4352 floats

__device__ __forceinline__ void cp_async16(float* smem_dst, const float* gmem_src) {
    uint32_t d = (uint32_t)__cvta_generic_to_shared(smem_dst);
    asm volatile("cp.async.cg.shared.global [%0], [%1], 16;\n" :: "r"(d), "l"(gmem_src));
}
__device__ __forceinline__ void cp_commit() {
    asm volatile("cp.async.commit_group;\n");
}
template <int N>
__device__ __forceinline__ void cp_wait() {
    asm volatile("cp.async.wait_group %0;\n" :: "n"(N));
}
__device__ __forceinline__ uint32_t f2tf32(float f) {
    uint32_t r;
    asm("cvt.rna.tf32.f32 %0, %1;" : "=r"(r) : "f"(f));
    return r;
}
__device__ __forceinline__ void mma_tf32(float* c, const uint32_t* a, const uint32_t* b) {
    asm volatile(
        "mma.sync.aligned.m16n8k8.row.col.f32.tf32.tf32.f32 "
        "{%0,%1,%2,%3}, {%4,%5,%6,%7}, {%8,%9}, {%0,%1,%2,%3};\n"
        : "+f"(c[0]), "+f"(c[1]), "+f"(c[2]), "+f"(c[3])
        : "r"(a[0]), "r"(a[1]), "r"(a[2]), "r"(a[3]), "r"(b[0]), "r"(b[1]));
}

__global__ void __launch_bounds__(256, 2)
gemm_tf32_kernel(const float* __restrict__ A, const float* __restrict__ B,
                 float* __restrict__ C, int M, int N, int K) {
    extern __shared__ float smem[];
    float* As = smem;                  // [2][BM][AS_STRIDE]
    float* Bs = smem + 2 * AS_SIZE;    // [2][BK][BS_STRIDE]

    const int bn = blockIdx.x;   // N / BN (fast-varying -> A tile reuse in L2)
    const int bm = blockIdx.y;   // M / BM
    const int tid = threadIdx.x;

    // global->shared load mapping
    const int a_row = tid >> 3;          // 0..31
    const int a_col = (tid & 7) * 4;     // 0..28
    const int b_row = tid >> 5;          // 0..7
    const int b_col = (tid & 31) * 4;    // 0..124

    const float* Ablk = A + (size_t)(bm * BM) * K;
    const float* Bblk = B + (size_t)(bn * BN);

    auto load_tile = [&](int kt, int s) {
        const int k0 = kt * BK;
        const float* ag = Ablk + (size_t)a_row * K + k0 + a_col;
        float* as = As + s * AS_SIZE + a_row * AS_STRIDE + a_col;
        #pragma unroll
        for (int i = 0; i < 4; i++)
            cp_async16(as + 32 * i * AS_STRIDE, ag + (size_t)(32 * i) * K);
        const float* bg = Bblk + (size_t)(k0 + b_row) * N + b_col;
        float* bs = Bs + s * BS_SIZE + b_row * BS_STRIDE + b_col;
        #pragma unroll
        for (int i = 0; i < 4; i++)
            cp_async16(bs + 8 * i * BS_STRIDE, bg + (size_t)(8 * i) * N);
        cp_commit();
    };

    // warp/thread decomposition
    const int warp = tid >> 5, lane = tid & 31;
    const int wm = warp & 3;      // warp row: rows wm*32
    const int wn = warp >> 2;     // warp col: cols wn*64
    const int gid = lane >> 2;    // 0..7
    const int tig = lane & 3;     // 0..3

    float acc[2][8][4];
    #pragma unroll
    for (int i = 0; i < 2; i++)
        #pragma unroll
        for (int j = 0; j < 8; j++)
            #pragma unroll
            for (int r = 0; r < 4; r++) acc[i][j][r] = 0.f;

    const int T = K / BK;
    load_tile(0, 0);

    for (int t = 0; t < T; t++) {
        if (t + 1 < T) {
            load_tile(t + 1, (t + 1) & 1);
            cp_wait<1>();
        } else {
            cp_wait<0>();
        }
        __syncthreads();

        const float* as = As + (t & 1) * AS_SIZE;
        const float* bs = Bs + (t & 1) * BS_SIZE;

        #pragma unroll
        for (int kc = 0; kc < 4; kc++) {
            const int k = kc * 8;
            uint32_t af[2][4], bf[8][2];
            #pragma unroll
            for (int mt = 0; mt < 2; mt++) {
                const int m = wm * 32 + mt * 16;
                af[mt][0] = f2tf32(as[(m + gid)     * AS_STRIDE + k + tig]);
                af[mt][1] = f2tf32(as[(m + gid + 8) * AS_STRIDE + k + tig]);
                af[mt][2] = f2tf32(as[(m + gid)     * AS_STRIDE + k + tig + 4]);
                af[mt][3] = f2tf32(as[(m + gid + 8) * AS_STRIDE + k + tig + 4]);
            }
            #pragma unroll
            for (int nt = 0; nt < 8; nt++) {
                const int n = wn * 64 + nt * 8;
                bf[nt][0] = f2tf32(bs[(k + tig)     * BS_STRIDE + n + gid]);
                bf[nt][1] = f2tf32(bs[(k + tig + 4) * BS_STRIDE + n + gid]);
            }
            #pragma unroll
            for (int mt = 0; mt < 2; mt++)
                #pragma unroll
                for (int nt = 0; nt < 8; nt++)
                    mma_tf32(acc[mt][nt], af[mt], bf[nt]);
        }
        __syncthreads();
    }

    // epilogue
    float* c = C + (size_t)(bm * BM) * N + bn * BN;
    #pragma unroll
    for (int mt = 0; mt < 2; mt++) {
        const int m = wm * 32 + mt * 16 + gid;
        #pragma unroll
        for (int nt = 0; nt < 8; nt++) {
            const int n = wn * 64 + nt * 8 + 2 * tig;
            float2 v0 = make_float2(acc[mt][nt][0], acc[mt][nt][1]);
            float2 v1 = make_float2(acc[mt][nt][2], acc[mt][nt][3]);
            *reinterpret_cast<float2*>(c + (size_t)m * N + n)       = v0;
            *reinterpret_cast<float2*>(c + (size_t)(m + 8) * N + n) = v1;
        }
    }
}

// ============================================================
// launch
// ============================================================
extern "C" void kernel_launch(void* const* d_in, const int* in_sizes, int n_in,
                              void* d_out, int out_size) {
    const float* x       = (const float*)d_in[0];  // (S,B,H) fp32
    const float* scale   = (const float*)d_in[1];  // (H,)
    const float* ln_bias = (const float*)d_in[2];  // (H,)
    const float* kern    = (const float*)d_in[3];  // (H,F)

    const int H = in_sizes[1];
    const int M = in_sizes[0] / H;      // S*B = 32768
    const int F = in_sizes[3] / H;      // 1024

    float* out    = (float*)d_out;                  // (M,F) first
    float* ln_out = out + (size_t)M * F;            // (M,H) second

    // LayerNorm -> ln_out (also the GEMM A operand)
    ln_kernel<<<M, H / 4>>>(x, scale, ln_bias, ln_out, H);

    // GEMM: out = ln_out @ kern
    size_t smem = (size_t)2 * (AS_SIZE + BS_SIZE) * sizeof(float);  // 71680 B
    cudaFuncSetAttribute(gemm_tf32_kernel,
                         cudaFuncAttributeMaxDynamicSharedMemorySize, (int)smem);
    dim3 grid(F / BN, M / BM);
    gemm_tf32_kernel<<<grid, 256, smem>>>(ln_out, kern, out, M, F, H);
}

// round 3
// speedup vs baseline: 1.0431x; 1.0431x over previous
#include <cuda_runtime.h>
#include <cstdint>

#define LN_EPS 1e-6f

// Fixed problem shape: M = S*B = 32768, K = H = 1024, N = F = 1024
#define DIM_M 32768
#define DIM_K 1024
#define DIM_N 1024

// Scratch (allocation-free rule: __device__ globals)
__device__ float g_A[(size_t)DIM_M * DIM_K];  // tf32-rounded ln_out (GEMM A)
__device__ float g_B[(size_t)DIM_K * DIM_N];  // tf32-rounded kernel (K x N, k-major)

// ============================================================
// helpers
// ============================================================
__device__ __forceinline__ uint32_t f2tf32(float f) {
    uint32_t r;
    asm("cvt.rna.tf32.f32 %0, %1;" : "=r"(r) : "f"(f));
    return r;
}
__device__ __forceinline__ void cp16(uint32_t smem_dst, const float* g) {
    asm volatile("cp.async.cg.shared.global [%0], [%1], 16;\n" :: "r"(smem_dst), "l"(g));
}
__device__ __forceinline__ void cp_commit() {
    asm volatile("cp.async.commit_group;\n");
}
__device__ __forceinline__ void mma_tf32(float* c, const uint32_t* a, const uint32_t* b) {
    asm volatile(
        "mma.sync.aligned.m16n8k8.row.col.f32.tf32.tf32.f32 "
        "{%0,%1,%2,%3}, {%4,%5,%6,%7}, {%8,%9}, {%0,%1,%2,%3};\n"
        : "+f"(c[0]), "+f"(c[1]), "+f"(c[2]), "+f"(c[3])
        : "r"(a[0]), "r"(a[1]), "r"(a[2]), "r"(a[3]), "r"(b[0]), "r"(b[1]));
}

// ============================================================
// LayerNorm: one row (H=1024) per block of 256 threads, float4.
// Writes exact fp32 ln_out AND tf32-rounded copy into g_A.
// ============================================================
__global__ void ln_kernel(const float* __restrict__ x,
                          const float* __restrict__ scale,
                          const float* __restrict__ bias,
                          float* __restrict__ ln_out, int H) {
    int row = blockIdx.x;
    const float4* xr = reinterpret_cast<const float4*>(x + (size_t)row * H);
    float4 v = xr[threadIdx.x];

    float s  = v.x + v.y + v.z + v.w;
    float sq = v.x * v.x + v.y * v.y + v.z * v.z + v.w * v.w;
    #pragma unroll
    for (int o = 16; o > 0; o >>= 1) {
        s  += __shfl_xor_sync(0xffffffffu, s,  o);
        sq += __shfl_xor_sync(0xffffffffu, sq, o);
    }
    __shared__ float ssum[8], ssq[8];
    int wid = threadIdx.x >> 5, lid = threadIdx.x & 31;
    if (lid == 0) { ssum[wid] = s; ssq[wid] = sq; }
    __syncthreads();
    s = 0.f; sq = 0.f;
    #pragma unroll
    for (int i = 0; i < 8; i++) { s += ssum[i]; sq += ssq[i]; }

    float invH = 1.0f / (float)H;
    float mu   = s * invH;
    float var  = sq * invH - mu * mu;
    float rstd = rsqrtf(var + LN_EPS);

    float4 sc = reinterpret_cast<const float4*>(scale)[threadIdx.x];
    float4 bi = reinterpret_cast<const float4*>(bias)[threadIdx.x];
    float4 o;
    o.x = (v.x - mu) * rstd * sc.x + bi.x;
    o.y = (v.y - mu) * rstd * sc.y + bi.y;
    o.z = (v.z - mu) * rstd * sc.z + bi.z;
    o.w = (v.w - mu) * rstd * sc.w + bi.w;
    reinterpret_cast<float4*>(ln_out + (size_t)row * H)[threadIdx.x] = o;

    float4 a4;
    a4.x = __uint_as_float(f2tf32(o.x));
    a4.y = __uint_as_float(f2tf32(o.y));
    a4.z = __uint_as_float(f2tf32(o.z));
    a4.w = __uint_as_float(f2tf32(o.w));
    reinterpret_cast<float4*>(g_A + (size_t)row * H)[threadIdx.x] = a4;
}

// ============================================================
// Elementwise tf32-round the weight into g_B (K x N, k-major)
// ============================================================
__global__ void roundB_kernel(const float* __restrict__ B) {
    size_t i = (size_t)(blockIdx.x * blockDim.x + threadIdx.x) * 4;
    float4 v = *reinterpret_cast<const float4*>(B + i);
    float4 r;
    r.x = __uint_as_float(f2tf32(v.x));
    r.y = __uint_as_float(f2tf32(v.y));
    r.z = __uint_as_float(f2tf32(v.z));
    r.w = __uint_as_float(f2tf32(v.w));
    *reinterpret_cast<float4*>(g_B + i) = r;
}

// ============================================================
// TF32 GEMM (legacy mma.sync): C[M,N] = g_A[M,K] * g_B[K,N]
// BM=128 BN=256 BK=32; 256 threads, 8 warps as 2(m) x 4(n),
// warp tile 64x64, m16n8k8 tf32, 4-stage cp.async ring,
// pre-rounded operands -> zero cvt in inner loop.
// ============================================================
#define STAGES 4
#define BM 128
#define BN 256
#define BK 32
#define AS_STRIDE 36    // floats; bank = 4*gid+tig, bijective mod 32
#define BS_STRIDE 264   // floats; bank = 8*tig+gid, bijective mod 32
#define A_BYTES (BM * AS_STRIDE * 4)           // 18432
#define B_BYTES (BK * BS_STRIDE * 4)           // 33792
#define STAGE_B (A_BYTES + B_BYTES)            // 52224
#define GEMM_SMEM (STAGES * STAGE_B)           // 208896

__device__ __forceinline__ void load_stage(uint32_t sb, int slot, int kt,
                                           const float* Ag, const float* Bg, int tid) {
    uint32_t st = sb + slot * STAGE_B;
    const int k0 = kt * BK;
    // A: 128 rows x 32 floats (128B/row) = 1024 x 16B chunks / 256 thr = 4 each
    #pragma unroll
    for (int i = 0; i < 4; i++) {
        int c = i * 256 + tid;
        int row = c >> 3, j = c & 7;
        cp16(st + (uint32_t)(row * (AS_STRIDE * 4) + j * 16),
             Ag + (size_t)row * DIM_K + k0 + j * 4);
    }
    // B: 32 rows x 256 floats (1024B/row) = 2048 x 16B chunks / 256 thr = 8 each
    #pragma unroll
    for (int i = 0; i < 8; i++) {
        int c = i * 256 + tid;
        int row = c >> 6, j = c & 63;
        cp16(st + A_BYTES + (uint32_t)(row * (BS_STRIDE * 4) + j * 16),
             Bg + (size_t)(k0 + row) * DIM_N + j * 4);
    }
    cp_commit();
}

__global__ void __launch_bounds__(256, 1)
gemm_tf32(float* __restrict__ C) {
    extern __shared__ __align__(1024) char smem[];
    uint32_t sb;
    asm("{ .reg .u64 t; cvta.to.shared.u64 t, %1; cvt.u32.u64 %0, t; }"
        : "=r"(sb) : "l"(smem));

    const int tid  = threadIdx.x;
    const int warp = tid >> 5, lane = tid & 31;
    const int wm = warp >> 2;        // 0..1 -> m offset wm*64
    const int wn = warp & 3;         // 0..3 -> n offset wn*64
    const int gid = lane >> 2;       // 0..7
    const int tig = lane & 3;        // 0..3

    const int bm = blockIdx.y, bn = blockIdx.x;
    const float* Ag = g_A + (size_t)bm * BM * DIM_K;
    const float* Bg = g_B + (size_t)bn * BN;

    float acc[4][8][4];
    #pragma unroll
    for (int i = 0; i < 4; i++)
        #pragma unroll
        for (int j = 0; j < 8; j++)
            #pragma unroll
            for (int r = 0; r < 4; r++) acc[i][j][r] = 0.f;

    const int T = DIM_K / BK;   // 32
    load_stage(sb, 0, 0, Ag, Bg, tid);
    load_stage(sb, 1, 1, Ag, Bg, tid);
    load_stage(sb, 2, 2, Ag, Bg, tid);

    for (int t = 0; t < T; t++) {
        asm volatile("cp.async.wait_group 2;\n");
        __syncthreads();

        // refill freed slot (t-1)%4 with tile t+3 (sync above guarantees all
        // warps are done computing on it); always commit to keep group count
        if (t + 3 < T) load_stage(sb, (t + 3) & 3, t + 3, Ag, Bg, tid);
        else           cp_commit();

        const uint32_t* as  = reinterpret_cast<const uint32_t*>(smem + (t & 3) * STAGE_B);
        const uint32_t* bsm = reinterpret_cast<const uint32_t*>(smem + (t & 3) * STAGE_B + A_BYTES);

        #pragma unroll
        for (int kc = 0; kc < 4; kc++) {
            const int k = kc * 8;
            uint32_t a[4][4], b[8][2];
            #pragma unroll
            for (int mt = 0; mt < 4; mt++) {
                const int m = wm * 64 + mt * 16;
                a[mt][0] = as[(m + gid)     * AS_STRIDE + k + tig];
                a[mt][1] = as[(m + gid + 8) * AS_STRIDE + k + tig];
                a[mt][2] = as[(m + gid)     * AS_STRIDE + k + tig + 4];
                a[mt][3] = as[(m + gid + 8) * AS_STRIDE + k + tig + 4];
            }
            #pragma unroll
            for (int nt = 0; nt < 8; nt++) {
                const int n = wn * 64 + nt * 8;
                b[nt][0] = bsm[(k + tig)     * BS_STRIDE + n + gid];
                b[nt][1] = bsm[(k + tig + 4) * BS_STRIDE + n + gid];
            }
            #pragma unroll
            for (int mt = 0; mt < 4; mt++)
                #pragma unroll
                for (int nt = 0; nt < 8; nt++)
                    mma_tf32(acc[mt][nt], a[mt], b[nt]);
        }
        __syncthreads();
    }

    // epilogue: direct float2 stores
    float* Cb = C + (size_t)(bm * BM) * DIM_N + bn * BN;
    #pragma unroll
    for (int mt = 0; mt < 4; mt++) {
        const int m = wm * 64 + mt * 16 + gid;
        #pragma unroll
        for (int nt = 0; nt < 8; nt++) {
            const int n = wn * 64 + nt * 8 + 2 * tig;
            *reinterpret_cast<float2*>(Cb + (size_t)m * DIM_N + n) =
                make_float2(acc[mt][nt][0], acc[mt][nt][1]);
            *reinterpret_cast<float2*>(Cb + (size_t)(m + 8) * DIM_N + n) =
                make_float2(acc[mt][nt][2], acc[mt][nt][3]);
        }
    }
}

// ============================================================
// launch
// ============================================================
extern "C" void kernel_launch(void* const* d_in, const int* in_sizes, int n_in,
                              void* d_out, int out_size) {
    const float* x       = (const float*)d_in[0];  // (S,B,H)
    const float* scale   = (const float*)d_in[1];  // (H,)
    const float* ln_bias = (const float*)d_in[2];  // (H,)
    const float* kern    = (const float*)d_in[3];  // (H,F)

    const int H = in_sizes[1];
    const int M = in_sizes[0] / H;   // 32768
    const int F = in_sizes[3] / H;   // 1024

    float* out    = (float*)d_out;             // (M,F) first
    float* ln_out = out + (size_t)M * F;       // (M,H) second

    ln_kernel<<<M, H / 4>>>(x, scale, ln_bias, ln_out, H);
    roundB_kernel<<<(H * F) / (256 * 4), 256>>>(kern);

    cudaFuncSetAttribute(gemm_tf32, cudaFuncAttributeMaxDynamicSharedMemorySize, GEMM_SMEM);
    gemm_tf32<<<dim3(F / BN, M / BM), 256, GEMM_SMEM>>>(out);
}

// round 4
// speedup vs baseline: 1.0624x; 1.0186x over previous
#include <cuda_runtime.h>
#include <cstdint>

#define LN_EPS 1e-6f

// Fixed problem shape: M = S*B = 32768, K = H = 1024, N = F = 1024
#define DIM_M 32768
#define DIM_K 1024
#define DIM_N 1024

// Scratch (allocation-free rule: __device__ globals)
__device__ float g_A[(size_t)DIM_M * DIM_K];  // tf32-rounded ln_out (GEMM A)
__device__ float g_B[(size_t)DIM_K * DIM_N];  // tf32-rounded kernel (K x N)

// ============================================================
// helpers
// ============================================================
__device__ __forceinline__ uint32_t f2tf32(float f) {
    uint32_t r;
    asm("cvt.rna.tf32.f32 %0, %1;" : "=r"(r) : "f"(f));
    return r;
}
__device__ __forceinline__ void cp16(uint32_t smem_dst, const float* g) {
    asm volatile("cp.async.cg.shared.global [%0], [%1], 16;\n" :: "r"(smem_dst), "l"(g));
}
__device__ __forceinline__ void cp_commit() {
    asm volatile("cp.async.commit_group;\n");
}
__device__ __forceinline__ void mma_tf32(float* c, const uint32_t* a, const uint32_t* b) {
    asm volatile(
        "mma.sync.aligned.m16n8k8.row.col.f32.tf32.tf32.f32 "
        "{%0,%1,%2,%3}, {%4,%5,%6,%7}, {%8,%9}, {%0,%1,%2,%3};\n"
        : "+f"(c[0]), "+f"(c[1]), "+f"(c[2]), "+f"(c[3])
        : "r"(a[0]), "r"(a[1]), "r"(a[2]), "r"(a[3]), "r"(b[0]), "r"(b[1]));
}

// ============================================================
// LayerNorm: one row (H=1024) per block of 256 threads, float4.
// Writes exact fp32 ln_out AND tf32-rounded copy into g_A.
// ============================================================
__global__ void ln_kernel(const float* __restrict__ x,
                          const float* __restrict__ scale,
                          const float* __restrict__ bias,
                          float* __restrict__ ln_out, int H) {
    int row = blockIdx.x;
    const float4* xr = reinterpret_cast<const float4*>(x + (size_t)row * H);
    float4 v = xr[threadIdx.x];

    float s  = v.x + v.y + v.z + v.w;
    float sq = v.x * v.x + v.y * v.y + v.z * v.z + v.w * v.w;
    #pragma unroll
    for (int o = 16; o > 0; o >>= 1) {
        s  += __shfl_xor_sync(0xffffffffu, s,  o);
        sq += __shfl_xor_sync(0xffffffffu, sq, o);
    }
    __shared__ float ssum[8], ssq[8];
    int wid = threadIdx.x >> 5, lid = threadIdx.x & 31;
    if (lid == 0) { ssum[wid] = s; ssq[wid] = sq; }
    __syncthreads();
    s = 0.f; sq = 0.f;
    #pragma unroll
    for (int i = 0; i < 8; i++) { s += ssum[i]; sq += ssq[i]; }

    float invH = 1.0f / (float)H;
    float mu   = s * invH;
    float var  = sq * invH - mu * mu;
    float rstd = rsqrtf(var + LN_EPS);

    float4 sc = reinterpret_cast<const float4*>(scale)[threadIdx.x];
    float4 bi = reinterpret_cast<const float4*>(bias)[threadIdx.x];
    float4 o;
    o.x = (v.x - mu) * rstd * sc.x + bi.x;
    o.y = (v.y - mu) * rstd * sc.y + bi.y;
    o.z = (v.z - mu) * rstd * sc.z + bi.z;
    o.w = (v.w - mu) * rstd * sc.w + bi.w;
    reinterpret_cast<float4*>(ln_out + (size_t)row * H)[threadIdx.x] = o;

    float4 a4;
    a4.x = __uint_as_float(f2tf32(o.x));
    a4.y = __uint_as_float(f2tf32(o.y));
    a4.z = __uint_as_float(f2tf32(o.z));
    a4.w = __uint_as_float(f2tf32(o.w));
    reinterpret_cast<float4*>(g_A + (size_t)row * H)[threadIdx.x] = a4;
}

// ============================================================
// Elementwise tf32-round the weight into g_B (K x N)
// ============================================================
__global__ void roundB_kernel(const float* __restrict__ B) {
    size_t i = (size_t)(blockIdx.x * blockDim.x + threadIdx.x) * 4;
    float4 v = *reinterpret_cast<const float4*>(B + i);
    float4 r;
    r.x = __uint_as_float(f2tf32(v.x));
    r.y = __uint_as_float(f2tf32(v.y));
    r.z = __uint_as_float(f2tf32(v.z));
    r.w = __uint_as_float(f2tf32(v.w));
    *reinterpret_cast<float4*>(g_B + i) = r;
}

// ============================================================
// TF32 GEMM (legacy mma.sync): C[M,N] = g_A[M,K] * g_B[K,N]
// BM=128 BN=128 BK=32; 128 threads (4 warps, 2x2), warp tile
// 64x64, m16n8k8, 3-stage cp.async ring, 2 CTAs/SM,
// pre-rounded operands -> zero cvt in inner loop.
// ============================================================
#define STAGES 3
#define BM 128
#define BN 128
#define BK 32
#define AS_STRIDE 36    // floats; bank = 4*gid+tig, bijective mod 32
#define BS_STRIDE 136   // floats; bank = 8*tig+gid, bijective mod 32
#define A_BYTES (BM * AS_STRIDE * 4)     // 18432
#define B_BYTES (BK * BS_STRIDE * 4)     // 17408
#define STAGE_B (A_BYTES + B_BYTES)      // 35840
#define GEMM_SMEM (STAGES * STAGE_B)     // 107520 -> 2 CTAs/SM

__device__ __forceinline__ void load_stage(uint32_t sb, int slot, int kt,
                                           const float* Ag, const float* Bg, int tid) {
    uint32_t st = sb + slot * STAGE_B;
    const int k0 = kt * BK;
    // A: 128 rows x 8 chunks(16B) = 1024 chunks / 128 thr = 8 each
    #pragma unroll
    for (int i = 0; i < 8; i++) {
        int c = i * 128 + tid;
        int row = c >> 3, j = c & 7;
        cp16(st + (uint32_t)(row * (AS_STRIDE * 4) + j * 16),
             Ag + (size_t)row * DIM_K + k0 + j * 4);
    }
    // B: 32 rows x 32 chunks(16B) = 1024 chunks / 128 thr = 8 each
    #pragma unroll
    for (int i = 0; i < 8; i++) {
        int c = i * 128 + tid;
        int row = c >> 5, j = c & 31;
        cp16(st + A_BYTES + (uint32_t)(row * (BS_STRIDE * 4) + j * 16),
             Bg + (size_t)(k0 + row) * DIM_N + j * 4);
    }
    cp_commit();
}

__global__ void __launch_bounds__(128, 2)
gemm_tf32(float* __restrict__ C) {
    extern __shared__ __align__(1024) char smem[];
    uint32_t sb;
    asm("{ .reg .u64 t; cvta.to.shared.u64 t, %1; cvt.u32.u64 %0, t; }"
        : "=r"(sb) : "l"(smem));

    const int tid  = threadIdx.x;
    const int warp = tid >> 5, lane = tid & 31;
    const int wm = warp >> 1;        // 0..1 -> m offset wm*64
    const int wn = warp & 1;         // 0..1 -> n offset wn*64
    const int gid = lane >> 2;       // 0..7
    const int tig = lane & 3;        // 0..3

    const int bm = blockIdx.y, bn = blockIdx.x;
    const float* Ag = g_A + (size_t)bm * BM * DIM_K;
    const float* Bg = g_B + (size_t)bn * BN;

    float acc[4][8][4];
    #pragma unroll
    for (int i = 0; i < 4; i++)
        #pragma unroll
        for (int j = 0; j < 8; j++)
            #pragma unroll
            for (int r = 0; r < 4; r++) acc[i][j][r] = 0.f;

    const int T = DIM_K / BK;   // 32
    load_stage(sb, 0, 0, Ag, Bg, tid);
    load_stage(sb, 1, 1, Ag, Bg, tid);

    for (int t = 0; t < T; t++) {
        asm volatile("cp.async.wait_group 1;\n");
        __syncthreads();
        // slot (t+2)%3 == slot of tile t-1; the wait+sync above proves every
        // warp finished computing tile t-1 (done in the previous iteration),
        // so the refill is safe with a single sync per tile.
        if (t + 2 < T) load_stage(sb, (t + 2) % 3, t + 2, Ag, Bg, tid);
        else           cp_commit();

        const uint32_t* as  = reinterpret_cast<const uint32_t*>(smem + (t % 3) * STAGE_B);
        const uint32_t* bsm = reinterpret_cast<const uint32_t*>(smem + (t % 3) * STAGE_B + A_BYTES);

        #pragma unroll
        for (int kc = 0; kc < 4; kc++) {
            const int k = kc * 8;
            uint32_t a[4][4], b[8][2];
            #pragma unroll
            for (int mt = 0; mt < 4; mt++) {
                const int m = wm * 64 + mt * 16;
                a[mt][0] = as[(m + gid)     * AS_STRIDE + k + tig];
                a[mt][1] = as[(m + gid + 8) * AS_STRIDE + k + tig];
                a[mt][2] = as[(m + gid)     * AS_STRIDE + k + tig + 4];
                a[mt][3] = as[(m + gid + 8) * AS_STRIDE + k + tig + 4];
            }
            #pragma unroll
            for (int nt = 0; nt < 8; nt++) {
                const int n = wn * 64 + nt * 8;
                b[nt][0] = bsm[(k + tig)     * BS_STRIDE + n + gid];
                b[nt][1] = bsm[(k + tig + 4) * BS_STRIDE + n + gid];
            }
            #pragma unroll
            for (int mt = 0; mt < 4; mt++)
                #pragma unroll
                for (int nt = 0; nt < 8; nt++)
                    mma_tf32(acc[mt][nt], a[mt], b[nt]);
        }
        __syncthreads();
    }

    // epilogue: direct float2 stores
    float* Cb = C + (size_t)(bm * BM) * DIM_N + bn * BN;
    #pragma unroll
    for (int mt = 0; mt < 4; mt++) {
        const int m = wm * 64 + mt * 16 + gid;
        #pragma unroll
        for (int nt = 0; nt < 8; nt++) {
            const int n = wn * 64 + nt * 8 + 2 * tig;
            *reinterpret_cast<float2*>(Cb + (size_t)m * DIM_N + n) =
                make_float2(acc[mt][nt][0], acc[mt][nt][1]);
            *reinterpret_cast<float2*>(Cb + (size_t)(m + 8) * DIM_N + n) =
                make_float2(acc[mt][nt][2], acc[mt][nt][3]);
        }
    }
}

// ============================================================
// launch
// ============================================================
extern "C" void kernel_launch(void* const* d_in, const int* in_sizes, int n_in,
                              void* d_out, int out_size) {
    const float* x       = (const float*)d_in[0];  // (S,B,H)
    const float* scale   = (const float*)d_in[1];  // (H,)
    const float* ln_bias = (const float*)d_in[2];  // (H,)
    const float* kern    = (const float*)d_in[3];  // (H,F)

    const int H = in_sizes[1];
    const int M = in_sizes[0] / H;   // 32768
    const int F = in_sizes[3] / H;   // 1024

    float* out    = (float*)d_out;             // (M,F) first
    float* ln_out = out + (size_t)M * F;       // (M,H) second

    ln_kernel<<<M, H / 4>>>(x, scale, ln_bias, ln_out, H);
    roundB_kernel<<<(H * F) / (256 * 4), 256>>>(kern);

    cudaFuncSetAttribute(gemm_tf32, cudaFuncAttributeMaxDynamicSharedMemorySize, GEMM_SMEM);
    gemm_tf32<<<dim3(F / BN, M / BM), 128, GEMM_SMEM>>>(out);
}